// round 15
// baseline (speedup 1.0000x reference)
#include <cuda_runtime.h>
#include <math.h>

typedef unsigned long long ull;

// Problem constants
#define Bk   4
#define Ck   256
#define BNk  64
#define Hk   128
#define Wk   128
#define HWk  16384
#define K2k  9

// -------- packed f32x2 helpers (Blackwell FFMA2) --------
__device__ __forceinline__ void ffma2(ull& d, ull a, ull b) {
    asm("fma.rn.f32x2 %0, %1, %2, %0;" : "+l"(d) : "l"(a), "l"(b));
}
__device__ __forceinline__ ull pack2(float v) {
    ull r; asm("mov.b64 %0, {%1, %1};" : "=l"(r) : "f"(v)); return r;
}
__device__ __forceinline__ ull pack2(float a, float b) {
    ull r; asm("mov.b64 %0, {%1, %2};" : "=l"(r) : "f"(a), "f"(b)); return r;
}
__device__ __forceinline__ float2 unpack2(ull v) {
    float2 f; asm("mov.b64 {%0, %1}, %2;" : "=f"(f.x), "=f"(f.y) : "l"(v)); return f;
}

// -------- scratch (device globals; no allocations allowed) --------
__device__ float g_z   [Bk * BNk * HWk];   // down-proj output (NCHW)
__device__ float g_d   [Bk * BNk * HWk];   // deform-conv output (NCHW)
__device__ float g_off [Bk * 18  * HWk];   // offsets
__device__ float g_mask[Bk * 9   * HWk];   // sigmoid(mask)
__device__ float g_dwT [Ck * BNk];         // down_w transposed: [c][o]
__device__ float g_uwT [BNk * Ck];         // up_w transposed: [c][oc]
__device__ float g_wbT [BNk * 9 * 32];     // off/mask weights: [(ic*9+tap)*32 + oc]
__device__ float g_wbBias[32];             // 18 off_b + 9 mask_b + pad
__device__ float g_wdT [9 * BNk * BNk];    // def_w: [(k*64+c)*64 + o]
__device__ float g_sum [Ck];
__device__ float g_sumsq[Ck];

// -------- prep: transpose/repack weights, zero stats --------
__global__ void prep_kernel(const float* __restrict__ down_w,
                            const float* __restrict__ off_w,
                            const float* __restrict__ off_b,
                            const float* __restrict__ mask_w,
                            const float* __restrict__ mask_b,
                            const float* __restrict__ def_w,
                            const float* __restrict__ up_w) {
    int i = blockIdx.x * 256 + threadIdx.x;
    if (i < Ck) { g_sum[i] = 0.f; g_sumsq[i] = 0.f; }
    if (i < Ck * BNk) {                 // down_w [64][256] -> [c][o]
        int o = i >> 8, c = i & 255;
        g_dwT[c * 64 + o] = down_w[i];
        // up_w [256][64] -> [c][oc]
        int oc = i >> 6, cc = i & 63;
        g_uwT[cc * 256 + oc] = up_w[i];
    }
    if (i < BNk * 9 * 32) {             // off/mask weights
        int oc = i & 31; int rest = i >> 5;
        int tap = rest % 9, ic = rest / 9;
        float v = 0.f;
        if (oc < 18)      v = off_w [(oc * 64 + ic) * 9 + tap];
        else if (oc < 27) v = mask_w[((oc - 18) * 64 + ic) * 9 + tap];
        g_wbT[i] = v;
    }
    if (i < 32) {
        float v = 0.f;
        if (i < 18)      v = off_b[i];
        else if (i < 27) v = mask_b[i - 18];
        g_wbBias[i] = v;
    }
    if (i < BNk * BNk * 9) {            // def_w [o][c][k] -> [(k*64+c)*64+o]
        int o = i / 576, rem = i % 576, c = rem / 9, k = rem % 9;
        g_wdT[(k * 64 + c) * 64 + o] = def_w[i];
    }
}

// 16 FFMA2: 4 px (dup-pairs va/vb) x 8 oc (pairs wa/wb)
#define GEMM16(A, wa, wb, va, vb)                                 \
    ffma2(A[0][0], wa.x, va.x); ffma2(A[0][1], wa.y, va.x);       \
    ffma2(A[0][2], wb.x, va.x); ffma2(A[0][3], wb.y, va.x);       \
    ffma2(A[1][0], wa.x, va.y); ffma2(A[1][1], wa.y, va.y);       \
    ffma2(A[1][2], wb.x, va.y); ffma2(A[1][3], wb.y, va.y);       \
    ffma2(A[2][0], wa.x, vb.x); ffma2(A[2][1], wa.y, vb.x);       \
    ffma2(A[2][2], wb.x, vb.x); ffma2(A[2][3], wb.y, vb.x);       \
    ffma2(A[3][0], wa.x, vb.y); ffma2(A[3][1], wa.y, vb.y);       \
    ffma2(A[3][2], wb.x, vb.y); ffma2(A[3][3], wb.y, vb.y);

// -------- kernel A: 1x1 down conv (256->64), dup-pair smem GEMM -------------
__global__ void __launch_bounds__(256, 4) down_kernel(const float* __restrict__ x) {
    __shared__ __align__(16) ull   vsm2[32][128];   // 32KB dup-pair values
    __shared__ __align__(16) float wsm[32 * 64];    // 8KB weights chunk
    int tid = threadIdx.x;
    int og  = tid >> 5;                // oc group: [og*8, og*8+8)
    int q   = tid & 31;                // pixel group: px 4q..4q+3
    int bp  = blockIdx.x * 128;
    int b   = bp >> 14;
    int p0  = bp & 16383;

    ull acc2[4][4];
#pragma unroll
    for (int j = 0; j < 4; j++)
#pragma unroll
        for (int o2 = 0; o2 < 4; o2++) acc2[j][o2] = 0ull;

    const float* xb = x + (size_t)b * Ck * HWk + p0;

    for (int c0 = 0; c0 < Ck; c0 += 32) {
        __syncthreads();
        {   // stage weights: 512 float4
            const float4* wsrc = reinterpret_cast<const float4*>(g_dwT + c0 * 64);
            float4* wdst = reinterpret_cast<float4*>(wsm);
#pragma unroll
            for (int j = tid; j < 512; j += 256) wdst[j] = wsrc[j];
        }
        {   // stage x tile as dup pairs: 32 ch x 32 float4
#pragma unroll
            for (int j = tid; j < 1024; j += 256) {
                int c = j >> 5, x4 = j & 31;
                float4 v = *reinterpret_cast<const float4*>(xb + (size_t)(c0 + c) * HWk + x4 * 4);
                ulonglong2* dst = reinterpret_cast<ulonglong2*>(&vsm2[c][x4 << 2]);
                dst[0] = make_ulonglong2(pack2(v.x), pack2(v.y));
                dst[1] = make_ulonglong2(pack2(v.z), pack2(v.w));
            }
        }
        __syncthreads();

#pragma unroll 2
        for (int c = 0; c < 32; c++) {
            const ulonglong2* vv = reinterpret_cast<const ulonglong2*>(&vsm2[c][q << 2]);
            ulonglong2 va = vv[0], vb = vv[1];
            const ulonglong2* wp = reinterpret_cast<const ulonglong2*>(wsm + c * 64 + og * 8);
            ulonglong2 wa = wp[0], wb = wp[1];
            GEMM16(acc2, wa, wb, va, vb);
        }
    }

    float* zb = g_z + (size_t)b * BNk * HWk + p0 + (q << 2);
#pragma unroll
    for (int o2 = 0; o2 < 4; o2++) {
        float2 f0 = unpack2(acc2[0][o2]);
        float2 f1 = unpack2(acc2[1][o2]);
        float2 f2 = unpack2(acc2[2][o2]);
        float2 f3 = unpack2(acc2[3][o2]);
        *reinterpret_cast<float4*>(zb + (size_t)(og * 8 + 2 * o2)     * HWk) =
            make_float4(f0.x, f1.x, f2.x, f3.x);
        *reinterpret_cast<float4*>(zb + (size_t)(og * 8 + 2 * o2 + 1) * HWk) =
            make_float4(f0.y, f1.y, f2.y, f3.y);
    }
}

// -------- kernel B: 3x3 conv -> offsets(18) + sigmoid(mask)(9), f32x2 -------
__global__ void __launch_bounds__(256) offmask_kernel() {
    __shared__ __align__(16) float zs[8][4][132];   // halo: 8 ic x 4 rows
    __shared__ __align__(16) float wsm[8 * 9 * 32]; // weights chunk
    int tid = threadIdx.x;
    int r0  = tid >> 7;         // 0/1: which output row
    int tx  = tid & 127;        // x coordinate
    int by  = blockIdx.x;       // row pair
    int b   = blockIdx.y;
    int y   = by * 2 + r0;

    ull acc2[14];
#pragma unroll
    for (int j = 0; j < 14; j++) acc2[j] = pack2(g_wbBias[2 * j], g_wbBias[2 * j + 1]);

    const float* zb = g_z + (size_t)b * BNk * HWk;

#pragma unroll 1
    for (int ic0 = 0; ic0 < 64; ic0 += 8) {
        __syncthreads();
        const float4* wsrc = reinterpret_cast<const float4*>(g_wbT + ic0 * 9 * 32);
        float4* wdst = reinterpret_cast<float4*>(wsm);
#pragma unroll
        for (int j = tid; j < 576; j += 256) wdst[j] = wsrc[j];
#pragma unroll
        for (int j = tid; j < 8 * 4 * 128; j += 256) {
            int ic = j >> 9;
            int r  = (j >> 7) & 3;
            int xx = j & 127;
            int yy = by * 2 + r - 1;
            zs[ic][r][xx + 1] = (yy >= 0 && yy < Hk)
                ? __ldg(zb + (size_t)(ic0 + ic) * HWk + yy * Wk + xx) : 0.f;
        }
        if (tid < 32) {
            int ic = tid >> 2, r = tid & 3;
            zs[ic][r][0] = 0.f; zs[ic][r][129] = 0.f;
        }
        __syncthreads();

#pragma unroll 1
        for (int ic = 0; ic < 8; ic++) {
#pragma unroll
            for (int tap = 0; tap < 9; tap++) {
                int ky = tap / 3, kx = tap % 3;
                ull zp = pack2(zs[ic][r0 + ky][tx + kx]);
                const ulonglong2* w2 = reinterpret_cast<const ulonglong2*>(wsm + (ic * 9 + tap) * 32);
                ulonglong2 wA = w2[0], wB = w2[1], wC = w2[2], wD = w2[3];
                ulonglong2 wE = w2[4], wF = w2[5], wG = w2[6];
                ffma2(acc2[0],  wA.x, zp); ffma2(acc2[1],  wA.y, zp);
                ffma2(acc2[2],  wB.x, zp); ffma2(acc2[3],  wB.y, zp);
                ffma2(acc2[4],  wC.x, zp); ffma2(acc2[5],  wC.y, zp);
                ffma2(acc2[6],  wD.x, zp); ffma2(acc2[7],  wD.y, zp);
                ffma2(acc2[8],  wE.x, zp); ffma2(acc2[9],  wE.y, zp);
                ffma2(acc2[10], wF.x, zp); ffma2(acc2[11], wF.y, zp);
                ffma2(acc2[12], wG.x, zp); ffma2(acc2[13], wG.y, zp);
            }
        }
    }

    int p = y * Wk + tx;
    float* offp = g_off + (size_t)b * 18 * HWk + p;
#pragma unroll
    for (int j = 0; j < 9; j++) {
        float2 f = unpack2(acc2[j]);
        offp[(size_t)(2 * j)     * HWk] = f.x;
        offp[(size_t)(2 * j + 1) * HWk] = f.y;
    }
    float* mp = g_mask + (size_t)b * 9 * HWk + p;
#pragma unroll
    for (int j = 9; j < 14; j++) {
        float2 f = unpack2(acc2[j]);
        int m = 2 * j - 18;
        mp[(size_t)m * HWk] = 1.f / (1.f + __expf(-f.x));
        if (m + 1 < 9) mp[(size_t)(m + 1) * HWk] = 1.f / (1.f + __expf(-f.y));
    }
}

// -------- kernel C: deform conv, phase-chunked gather + dup-pair GEMM -------
__global__ void __launch_bounds__(256, 4) deform_kernel(const float* __restrict__ def_b) {
    __shared__ __align__(16) ull   vsm2[32][128];   // 32KB dup-pair samples
    __shared__ __align__(16) float wsm[32 * 64];    // 8KB weights chunk
    int tid  = threadIdx.x;
    int half = tid >> 7;        // gather: channel sub-range
    int tx   = tid & 127;       // gather pixel
    int og   = tid >> 5;        // GEMM: 8 oc
    int q    = tid & 31;        // GEMM pixel group
    int bp   = blockIdx.x * 128;
    int b    = bp >> 14;
    int p0   = bp & 16383;
    int gy   = (p0 + tx) >> 7;
    int gx   = (p0 + tx) & 127;

    const float* zb   = g_z    + (size_t)b * BNk * HWk;
    const float* offp = g_off  + (size_t)b * 18  * HWk + p0 + tx;
    const float* mp   = g_mask + (size_t)b * 9   * HWk + p0 + tx;

    ull acc2[4][4];
#pragma unroll
    for (int o2 = 0; o2 < 4; o2++) {
        ull bb = pack2(__ldg(def_b + og * 8 + 2 * o2), __ldg(def_b + og * 8 + 2 * o2 + 1));
#pragma unroll
        for (int j = 0; j < 4; j++) acc2[j][o2] = bb;
    }

#pragma unroll 1
    for (int k = 0; k < 9; k++) {
#pragma unroll 1
        for (int ph = 0; ph < 2; ph++) {
            __syncthreads();   // previous GEMM done before overwriting smem
            {   // stage this chunk's weights: rows ph*32..+32 of tap k
                const float4* wk4 = reinterpret_cast<const float4*>(g_wdT + (k * 64 + ph * 32) * 64);
                float4* wdst = reinterpret_cast<float4*>(wsm);
#pragma unroll
                for (int j = tid; j < 512; j += 256) wdst[j] = wk4[j];
            }
            {   // bilinear gather: 16 channels per thread
                int ky = k / 3, kx = k % 3;
                float dy = __ldg(offp + (size_t)(2 * k)     * HWk);
                float dx = __ldg(offp + (size_t)(2 * k + 1) * HWk);
                float mk = __ldg(mp   + (size_t)k           * HWk);

                float py = dy + (float)(gy + ky - 1);
                float px = dx + (float)(gx + kx - 1);
                float y0f = floorf(py), x0f = floorf(px);
                float wy = py - y0f, wx = px - x0f;
                int y0 = (int)y0f, x0 = (int)x0f;
                int y1 = y0 + 1,   x1 = x0 + 1;
                bool vy0 = (y0 >= 0) && (y0 < Hk), vy1 = (y1 >= 0) && (y1 < Hk);
                bool vx0 = (x0 >= 0) && (x0 < Wk), vx1 = (x1 >= 0) && (x1 < Wk);
                float a00 = (1.f - wy) * (1.f - wx) * mk * ((vy0 && vx0) ? 1.f : 0.f);
                float a01 = (1.f - wy) * wx         * mk * ((vy0 && vx1) ? 1.f : 0.f);
                float a10 = wy         * (1.f - wx) * mk * ((vy1 && vx0) ? 1.f : 0.f);
                float a11 = wy         * wx         * mk * ((vy1 && vx1) ? 1.f : 0.f);
                int yc0 = min(max(y0, 0), Hk - 1), yc1 = min(max(y1, 0), Hk - 1);
                int xc0 = min(max(x0, 0), Wk - 1), xc1 = min(max(x1, 0), Wk - 1);
                int i00 = yc0 * Wk + xc0, i01 = yc0 * Wk + xc1;
                int i10 = yc1 * Wk + xc0, i11 = yc1 * Wk + xc1;

                const float* zh = zb + (size_t)(ph * 32 + half * 16) * HWk;
#pragma unroll 4
                for (int c = 0; c < 16; c++) {
                    const float* zc = zh + (size_t)c * HWk;
                    float v = a00 * __ldg(zc + i00) + a01 * __ldg(zc + i01)
                            + a10 * __ldg(zc + i10) + a11 * __ldg(zc + i11);
                    vsm2[half * 16 + c][tx] = pack2(v);
                }
            }
            __syncthreads();

            // GEMM: 32 c-steps, 4 px x 8 oc per thread
#pragma unroll 2
            for (int c = 0; c < 32; c++) {
                const ulonglong2* vv = reinterpret_cast<const ulonglong2*>(&vsm2[c][q << 2]);
                ulonglong2 va = vv[0], vb = vv[1];
                const ulonglong2* wp = reinterpret_cast<const ulonglong2*>(wsm + c * 64 + og * 8);
                ulonglong2 wa = wp[0], wb = wp[1];
                GEMM16(acc2, wa, wb, va, vb);
            }
        }
    }

    float* dbp = g_d + (size_t)b * BNk * HWk + p0 + (q << 2);
#pragma unroll
    for (int o2 = 0; o2 < 4; o2++) {
        float2 f0 = unpack2(acc2[0][o2]);
        float2 f1 = unpack2(acc2[1][o2]);
        float2 f2 = unpack2(acc2[2][o2]);
        float2 f3 = unpack2(acc2[3][o2]);
        *reinterpret_cast<float4*>(dbp + (size_t)(og * 8 + 2 * o2)     * HWk) =
            make_float4(f0.x, f1.x, f2.x, f3.x);
        *reinterpret_cast<float4*>(dbp + (size_t)(og * 8 + 2 * o2 + 1) * HWk) =
            make_float4(f0.y, f1.y, f2.y, f3.y);
    }
}

// -------- kernel D: 1x1 up conv + residual + BN stats ------------------------
__global__ void __launch_bounds__(256, 4) up_kernel(const float* __restrict__ x,
                                                    float* __restrict__ out) {
    __shared__ __align__(16) ull   vsm2[32][128];   // 32KB dup-pair d values
    __shared__ __align__(16) float wsm[32 * 64];    // 8KB weights chunk
    int tid = threadIdx.x;
    int og  = tid >> 5;
    int q   = tid & 31;
    int oh  = blockIdx.y;             // oc quarter: [oh*64, oh*64+64)
    int bp  = blockIdx.x * 128;
    int b   = bp >> 14;
    int p0  = bp & 16383;

    ull acc2[4][4];
#pragma unroll
    for (int j = 0; j < 4; j++)
#pragma unroll
        for (int o2 = 0; o2 < 4; o2++) acc2[j][o2] = 0ull;

    const float* db = g_d + (size_t)b * BNk * HWk + p0;

#pragma unroll 1
    for (int c0 = 0; c0 < 64; c0 += 32) {
        __syncthreads();
        {   // stage weights: wsm[c][oi] = g_uwT[(c0+c)*256 + oh*64 + oi]
            const float4* usrc = reinterpret_cast<const float4*>(g_uwT);
            float4* wdst = reinterpret_cast<float4*>(wsm);
#pragma unroll
            for (int j = tid; j < 512; j += 256) {
                int c = j >> 4, o4 = j & 15;
                wdst[j] = usrc[(c0 + c) * 64 + oh * 16 + o4];
            }
        }
        {   // stage d tile as dup pairs
#pragma unroll
            for (int j = tid; j < 1024; j += 256) {
                int c = j >> 5, x4 = j & 31;
                float4 v = *reinterpret_cast<const float4*>(db + (size_t)(c0 + c) * HWk + x4 * 4);
                ulonglong2* dst = reinterpret_cast<ulonglong2*>(&vsm2[c][x4 << 2]);
                dst[0] = make_ulonglong2(pack2(v.x), pack2(v.y));
                dst[1] = make_ulonglong2(pack2(v.z), pack2(v.w));
            }
        }
        __syncthreads();

#pragma unroll 2
        for (int c = 0; c < 32; c++) {
            const ulonglong2* vv = reinterpret_cast<const ulonglong2*>(&vsm2[c][q << 2]);
            ulonglong2 va = vv[0], vb = vv[1];
            const ulonglong2* wp = reinterpret_cast<const ulonglong2*>(wsm + c * 64 + og * 8);
            ulonglong2 wa = wp[0], wb = wp[1];
            GEMM16(acc2, wa, wb, va, vb);
        }
    }

    // epilogue: +x, write, BN partial sums
    const float* xb = x   + (size_t)b * Ck * HWk + p0 + (q << 2);
    float*       ob = out + (size_t)b * Ck * HWk + p0 + (q << 2);
#pragma unroll
    for (int o2 = 0; o2 < 4; o2++) {
        int oc0 = oh * 64 + og * 8 + 2 * o2;
        float2 f0 = unpack2(acc2[0][o2]);
        float2 f1 = unpack2(acc2[1][o2]);
        float2 f2 = unpack2(acc2[2][o2]);
        float2 f3 = unpack2(acc2[3][o2]);
        float4 xlo = *reinterpret_cast<const float4*>(xb + (size_t)oc0       * HWk);
        float4 xhi = *reinterpret_cast<const float4*>(xb + (size_t)(oc0 + 1) * HWk);
        float4 lo = make_float4(xlo.x + f0.x, xlo.y + f1.x, xlo.z + f2.x, xlo.w + f3.x);
        float4 hi = make_float4(xhi.x + f0.y, xhi.y + f1.y, xhi.z + f2.y, xhi.w + f3.y);
        *reinterpret_cast<float4*>(ob + (size_t)oc0       * HWk) = lo;
        *reinterpret_cast<float4*>(ob + (size_t)(oc0 + 1) * HWk) = hi;

        float ws0 = lo.x + lo.y + lo.z + lo.w;
        float wq0 = lo.x * lo.x + lo.y * lo.y + lo.z * lo.z + lo.w * lo.w;
        float ws1 = hi.x + hi.y + hi.z + hi.w;
        float wq1 = hi.x * hi.x + hi.y * hi.y + hi.z * hi.z + hi.w * hi.w;
#pragma unroll
        for (int d = 16; d; d >>= 1) {
            ws0 += __shfl_xor_sync(0xffffffffu, ws0, d);
            wq0 += __shfl_xor_sync(0xffffffffu, wq0, d);
            ws1 += __shfl_xor_sync(0xffffffffu, ws1, d);
            wq1 += __shfl_xor_sync(0xffffffffu, wq1, d);
        }
        if (q == 0) {
            atomicAdd(&g_sum[oc0],       ws0);
            atomicAdd(&g_sumsq[oc0],     wq0);
            atomicAdd(&g_sum[oc0 + 1],   ws1);
            atomicAdd(&g_sumsq[oc0 + 1], wq1);
        }
    }
}

// -------- kernel E: BatchNorm (training stats) + SiLU, in place --------
__global__ void __launch_bounds__(256) norm_kernel(float* __restrict__ out,
                                                   const float* __restrict__ gamma,
                                                   const float* __restrict__ beta) {
    const float invN = 1.f / (float)(Bk * HWk);   // 1/65536
    size_t i = (size_t)blockIdx.x * 256 + threadIdx.x;   // float4 index
    int ch = (int)((i >> 12) & 255);                      // 4096 float4 per channel

    float mean = g_sum[ch] * invN;
    float var  = g_sumsq[ch] * invN - mean * mean;
    float r    = rsqrtf(var + 1e-5f);
    float sc   = r * __ldg(gamma + ch);
    float sh   = __ldg(beta + ch) - mean * sc;

    float4* o4 = reinterpret_cast<float4*>(out);
    float4 v = o4[i];
    float h;
    h = v.x * sc + sh; v.x = h / (1.f + __expf(-h));
    h = v.y * sc + sh; v.y = h / (1.f + __expf(-h));
    h = v.z * sc + sh; v.z = h / (1.f + __expf(-h));
    h = v.w * sc + sh; v.w = h / (1.f + __expf(-h));
    o4[i] = v;
}

// -------- launch --------
extern "C" void kernel_launch(void* const* d_in, const int* in_sizes, int n_in,
                              void* d_out, int out_size) {
    const float* x      = (const float*)d_in[0];
    const float* down_w = (const float*)d_in[1];
    const float* off_w  = (const float*)d_in[2];
    const float* off_b  = (const float*)d_in[3];
    const float* mask_w = (const float*)d_in[4];
    const float* mask_b = (const float*)d_in[5];
    const float* def_w  = (const float*)d_in[6];
    const float* def_b  = (const float*)d_in[7];
    const float* up_w   = (const float*)d_in[8];
    const float* gamma  = (const float*)d_in[9];
    const float* beta   = (const float*)d_in[10];
    float* out = (float*)d_out;

    prep_kernel<<<144, 256>>>(down_w, off_w, off_b, mask_w, mask_b, def_w, up_w);
    down_kernel<<<512, 256>>>(x);
    offmask_kernel<<<dim3(Hk / 2, Bk), 256>>>();
    deform_kernel<<<512, 256>>>(def_b);
    up_kernel<<<dim3(512, 4), 256>>>(x, out);
    norm_kernel<<<(Bk * Ck * HWk) / 4 / 256, 256>>>(out, gamma, beta);
}

// round 16
// speedup vs baseline: 1.2182x; 1.2182x over previous
#include <cuda_runtime.h>
#include <math.h>

typedef unsigned long long ull;

// Problem constants
#define Bk   4
#define Ck   256
#define BNk  64
#define Hk   128
#define Wk   128
#define HWk  16384
#define K2k  9

// -------- packed f32x2 helpers (Blackwell FFMA2) --------
__device__ __forceinline__ void ffma2(ull& d, ull a, ull b) {
    asm("fma.rn.f32x2 %0, %1, %2, %0;" : "+l"(d) : "l"(a), "l"(b));
}
__device__ __forceinline__ ull pack2(float v) {
    ull r; asm("mov.b64 %0, {%1, %1};" : "=l"(r) : "f"(v)); return r;
}
__device__ __forceinline__ ull pack2(float a, float b) {
    ull r; asm("mov.b64 %0, {%1, %2};" : "=l"(r) : "f"(a), "f"(b)); return r;
}
__device__ __forceinline__ float2 unpack2(ull v) {
    float2 f; asm("mov.b64 {%0, %1}, %2;" : "=f"(f.x), "=f"(f.y) : "l"(v)); return f;
}

// 8 FFMA2: 2 px-pairs (va, vb) x 4 oc (dup-packed w01, w23)
#define GEMM8(A, w01, w23, va, vb)                            \
    ffma2(A[0][0], w01.x, va); ffma2(A[0][1], w01.y, va);     \
    ffma2(A[0][2], w23.x, va); ffma2(A[0][3], w23.y, va);     \
    ffma2(A[1][0], w01.x, vb); ffma2(A[1][1], w01.y, vb);     \
    ffma2(A[1][2], w23.x, vb); ffma2(A[1][3], w23.y, vb);

// -------- scratch (device globals; no allocations allowed) --------
__device__ float g_z   [Bk * BNk * HWk];   // down-proj output (NCHW)
__device__ float g_d   [Bk * BNk * HWk];   // deform-conv output (NCHW)
__device__ float g_off [Bk * 18  * HWk];   // offsets
__device__ float g_mask[Bk * 9   * HWk];   // sigmoid(mask)
__device__ float g_dwT [Ck * BNk];         // down_w transposed: [c][o]
__device__ float g_uwT [BNk * Ck];         // up_w transposed: [c][oc]
__device__ float g_wbT [BNk * 9 * 32];     // off/mask weights: [(ic*9+tap)*32 + oc]
__device__ float g_wbBias[32];             // 18 off_b + 9 mask_b + pad
__device__ float g_wdT [9 * BNk * BNk];    // def_w: [(k*64+c)*64 + o]
__device__ float g_sum [Ck];
__device__ float g_sumsq[Ck];

// -------- prep: transpose/repack weights, zero stats --------
__global__ void prep_kernel(const float* __restrict__ down_w,
                            const float* __restrict__ off_w,
                            const float* __restrict__ off_b,
                            const float* __restrict__ mask_w,
                            const float* __restrict__ mask_b,
                            const float* __restrict__ def_w,
                            const float* __restrict__ up_w) {
    int i = blockIdx.x * 256 + threadIdx.x;
    if (i < Ck) { g_sum[i] = 0.f; g_sumsq[i] = 0.f; }
    if (i < Ck * BNk) {                 // down_w [64][256] -> [c][o]
        int o = i >> 8, c = i & 255;
        g_dwT[c * 64 + o] = down_w[i];
        // up_w [256][64] -> [c][oc]
        int oc = i >> 6, cc = i & 63;
        g_uwT[cc * 256 + oc] = up_w[i];
    }
    if (i < BNk * 9 * 32) {             // off/mask weights
        int oc = i & 31; int rest = i >> 5;
        int tap = rest % 9, ic = rest / 9;
        float v = 0.f;
        if (oc < 18)      v = off_w [(oc * 64 + ic) * 9 + tap];
        else if (oc < 27) v = mask_w[((oc - 18) * 64 + ic) * 9 + tap];
        g_wbT[i] = v;
    }
    if (i < 32) {
        float v = 0.f;
        if (i < 18)      v = off_b[i];
        else if (i < 27) v = mask_b[i - 18];
        g_wbBias[i] = v;
    }
    if (i < BNk * BNk * 9) {            // def_w [o][c][k] -> [(k*64+c)*64+o]
        int o = i / 576, rem = i % 576, c = rem / 9, k = rem % 9;
        g_wdT[(k * 64 + c) * 64 + o] = def_w[i];
    }
}

// -------- kernel A: 1x1 down conv (256->64), 4px x 4oc, dup-packed weights --
__global__ void __launch_bounds__(256, 5) down_kernel(const float* __restrict__ x) {
    __shared__ __align__(16) float vsm[32][64];    // 8KB values
    __shared__ __align__(16) ull   wsm2[32][64];   // 16KB dup-packed weights
    int tid = threadIdx.x;
    int g   = tid & 15;          // px group: pairs (2g,2g+1),(32+2g,33+2g)
    int og  = tid >> 4;          // oc group: [og*4, og*4+4)
    int bp  = blockIdx.x * 64;
    int b   = bp >> 14;
    int p0  = bp & 16383;

    ull acc2[2][4];
#pragma unroll
    for (int j = 0; j < 2; j++)
#pragma unroll
        for (int o = 0; o < 4; o++) acc2[j][o] = 0ull;

    const float* xb = x + (size_t)b * Ck * HWk + p0;

    for (int c0 = 0; c0 < Ck; c0 += 32) {
        __syncthreads();
        {   // stage dup-packed weights: 512 float4 -> 1024 ulonglong2
            const float4* ws = reinterpret_cast<const float4*>(g_dwT + c0 * 64);
#pragma unroll
            for (int j = tid; j < 512; j += 256) {
                int c = j >> 4, o4 = j & 15;
                float4 w = ws[j];
                ulonglong2* dst = reinterpret_cast<ulonglong2*>(&wsm2[c][o4 * 4]);
                dst[0] = make_ulonglong2(pack2(w.x), pack2(w.y));
                dst[1] = make_ulonglong2(pack2(w.z), pack2(w.w));
            }
        }
        {   // stage x tile: 32c x 64px
#pragma unroll
            for (int j = tid; j < 512; j += 256) {
                int c = j >> 4, p4 = j & 15;
                *reinterpret_cast<float4*>(&vsm[c][p4 * 4]) =
                    *reinterpret_cast<const float4*>(xb + (size_t)(c0 + c) * HWk + p4 * 4);
            }
        }
        __syncthreads();

#pragma unroll 4
        for (int c = 0; c < 32; c++) {
            const ull* vp = reinterpret_cast<const ull*>(&vsm[c][0]);
            ull va = vp[g], vb = vp[16 + g];
            const ulonglong2* wp = reinterpret_cast<const ulonglong2*>(&wsm2[c][og * 4]);
            ulonglong2 w01 = wp[0], w23 = wp[1];
            GEMM8(acc2, w01, w23, va, vb);
        }
    }

    float* zb = g_z + (size_t)b * BNk * HWk + p0;
#pragma unroll
    for (int o = 0; o < 4; o++) {
        float2 f0 = unpack2(acc2[0][o]);
        float2 f1 = unpack2(acc2[1][o]);
        *reinterpret_cast<float2*>(zb + (size_t)(og * 4 + o) * HWk + 2 * g)      = f0;
        *reinterpret_cast<float2*>(zb + (size_t)(og * 4 + o) * HWk + 32 + 2 * g) = f1;
    }
}

// -------- kernel B: 3x3 conv -> offsets(18) + sigmoid(mask)(9), f32x2 -------
__global__ void __launch_bounds__(256) offmask_kernel() {
    __shared__ __align__(16) float zs[8][4][132];   // halo: 8 ic x 4 rows
    __shared__ __align__(16) float wsm[8 * 9 * 32]; // weights chunk
    int tid = threadIdx.x;
    int r0  = tid >> 7;         // 0/1: which output row
    int tx  = tid & 127;        // x coordinate
    int by  = blockIdx.x;       // row pair
    int b   = blockIdx.y;
    int y   = by * 2 + r0;

    ull acc2[14];
#pragma unroll
    for (int j = 0; j < 14; j++) acc2[j] = pack2(g_wbBias[2 * j], g_wbBias[2 * j + 1]);

    const float* zb = g_z + (size_t)b * BNk * HWk;

#pragma unroll 1
    for (int ic0 = 0; ic0 < 64; ic0 += 8) {
        __syncthreads();
        const float4* wsrc = reinterpret_cast<const float4*>(g_wbT + ic0 * 9 * 32);
        float4* wdst = reinterpret_cast<float4*>(wsm);
#pragma unroll
        for (int j = tid; j < 576; j += 256) wdst[j] = wsrc[j];
#pragma unroll
        for (int j = tid; j < 8 * 4 * 128; j += 256) {
            int ic = j >> 9;
            int r  = (j >> 7) & 3;
            int xx = j & 127;
            int yy = by * 2 + r - 1;
            zs[ic][r][xx + 1] = (yy >= 0 && yy < Hk)
                ? __ldg(zb + (size_t)(ic0 + ic) * HWk + yy * Wk + xx) : 0.f;
        }
        if (tid < 32) {
            int ic = tid >> 2, r = tid & 3;
            zs[ic][r][0] = 0.f; zs[ic][r][129] = 0.f;
        }
        __syncthreads();

#pragma unroll 1
        for (int ic = 0; ic < 8; ic++) {
#pragma unroll
            for (int tap = 0; tap < 9; tap++) {
                int ky = tap / 3, kx = tap % 3;
                ull zp = pack2(zs[ic][r0 + ky][tx + kx]);
                const ulonglong2* w2 = reinterpret_cast<const ulonglong2*>(wsm + (ic * 9 + tap) * 32);
                ulonglong2 wA = w2[0], wB = w2[1], wC = w2[2], wD = w2[3];
                ulonglong2 wE = w2[4], wF = w2[5], wG = w2[6];
                ffma2(acc2[0],  wA.x, zp); ffma2(acc2[1],  wA.y, zp);
                ffma2(acc2[2],  wB.x, zp); ffma2(acc2[3],  wB.y, zp);
                ffma2(acc2[4],  wC.x, zp); ffma2(acc2[5],  wC.y, zp);
                ffma2(acc2[6],  wD.x, zp); ffma2(acc2[7],  wD.y, zp);
                ffma2(acc2[8],  wE.x, zp); ffma2(acc2[9],  wE.y, zp);
                ffma2(acc2[10], wF.x, zp); ffma2(acc2[11], wF.y, zp);
                ffma2(acc2[12], wG.x, zp); ffma2(acc2[13], wG.y, zp);
            }
        }
    }

    int p = y * Wk + tx;
    float* offp = g_off + (size_t)b * 18 * HWk + p;
#pragma unroll
    for (int j = 0; j < 9; j++) {
        float2 f = unpack2(acc2[j]);
        offp[(size_t)(2 * j)     * HWk] = f.x;
        offp[(size_t)(2 * j + 1) * HWk] = f.y;
    }
    float* mp = g_mask + (size_t)b * 9 * HWk + p;
#pragma unroll
    for (int j = 9; j < 14; j++) {
        float2 f = unpack2(acc2[j]);
        int m = 2 * j - 18;
        mp[(size_t)m * HWk] = 1.f / (1.f + __expf(-f.x));
        if (m + 1 < 9) mp[(size_t)(m + 1) * HWk] = 1.f / (1.f + __expf(-f.y));
    }
}

// -------- kernel C: deform conv, 64px tile, 4px x 4oc, dup-packed weights ---
__global__ void __launch_bounds__(256, 4) deform_kernel(const float* __restrict__ def_b) {
    __shared__ __align__(16) float vsm[32][64];    // 8KB sampled values
    __shared__ __align__(16) ull   wsm2[32][64];   // 16KB dup-packed weights
    int tid = threadIdx.x;
    int g   = tid & 15;          // GEMM px group
    int og  = tid >> 4;          // GEMM oc group
    int tx  = tid & 63;          // gather pixel
    int quarter = tid >> 6;      // gather channel quarter
    int bp  = blockIdx.x * 64;
    int b   = bp >> 14;
    int p0  = bp & 16383;
    int gy  = (p0 + tx) >> 7;
    int gx  = (p0 + tx) & 127;

    const float* zb   = g_z    + (size_t)b * BNk * HWk;
    const float* offp = g_off  + (size_t)b * 18  * HWk + p0 + tx;
    const float* mp   = g_mask + (size_t)b * 9   * HWk + p0 + tx;

    ull acc2[2][4];
#pragma unroll
    for (int o = 0; o < 4; o++) {
        ull bb = pack2(__ldg(def_b + og * 4 + o));
        acc2[0][o] = bb; acc2[1][o] = bb;
    }

#pragma unroll 1
    for (int k = 0; k < 9; k++) {
        // bilinear coefficients once per tap (held in regs across phases)
        int ky = k / 3, kx = k % 3;
        float dy = __ldg(offp + (size_t)(2 * k)     * HWk);
        float dx = __ldg(offp + (size_t)(2 * k + 1) * HWk);
        float mk = __ldg(mp   + (size_t)k           * HWk);

        float py = dy + (float)(gy + ky - 1);
        float px = dx + (float)(gx + kx - 1);
        float y0f = floorf(py), x0f = floorf(px);
        float wy = py - y0f, wx = px - x0f;
        int y0 = (int)y0f, x0 = (int)x0f;
        int y1 = y0 + 1,   x1 = x0 + 1;
        bool vy0 = (y0 >= 0) && (y0 < Hk), vy1 = (y1 >= 0) && (y1 < Hk);
        bool vx0 = (x0 >= 0) && (x0 < Wk), vx1 = (x1 >= 0) && (x1 < Wk);
        float a00 = (1.f - wy) * (1.f - wx) * mk * ((vy0 && vx0) ? 1.f : 0.f);
        float a01 = (1.f - wy) * wx         * mk * ((vy0 && vx1) ? 1.f : 0.f);
        float a10 = wy         * (1.f - wx) * mk * ((vy1 && vx0) ? 1.f : 0.f);
        float a11 = wy         * wx         * mk * ((vy1 && vx1) ? 1.f : 0.f);
        int yc0 = min(max(y0, 0), Hk - 1), yc1 = min(max(y1, 0), Hk - 1);
        int xc0 = min(max(x0, 0), Wk - 1), xc1 = min(max(x1, 0), Wk - 1);
        int i00 = yc0 * Wk + xc0, i01 = yc0 * Wk + xc1;
        int i10 = yc1 * Wk + xc0, i11 = yc1 * Wk + xc1;

#pragma unroll 1
        for (int ph = 0; ph < 2; ph++) {
            __syncthreads();   // previous GEMM done before overwriting smem
            {   // stage dup-packed weights for rows [k*64+ph*32, +32)
                const float4* wk4 = reinterpret_cast<const float4*>(g_wdT + (k * 64 + ph * 32) * 64);
#pragma unroll
                for (int j = tid; j < 512; j += 256) {
                    int c = j >> 4, o4 = j & 15;
                    float4 w = wk4[j];
                    ulonglong2* dst = reinterpret_cast<ulonglong2*>(&wsm2[c][o4 * 4]);
                    dst[0] = make_ulonglong2(pack2(w.x), pack2(w.y));
                    dst[1] = make_ulonglong2(pack2(w.z), pack2(w.w));
                }
            }
            {   // gather: 8 channels per thread
                const float* zh = zb + (size_t)(ph * 32 + quarter * 8) * HWk;
#pragma unroll
                for (int c = 0; c < 8; c++) {
                    const float* zc = zh + (size_t)c * HWk;
                    float v = a00 * __ldg(zc + i00) + a01 * __ldg(zc + i01)
                            + a10 * __ldg(zc + i10) + a11 * __ldg(zc + i11);
                    vsm[quarter * 8 + c][tx] = v;
                }
            }
            __syncthreads();

#pragma unroll 4
            for (int c = 0; c < 32; c++) {
                const ull* vp = reinterpret_cast<const ull*>(&vsm[c][0]);
                ull va = vp[g], vb = vp[16 + g];
                const ulonglong2* wp = reinterpret_cast<const ulonglong2*>(&wsm2[c][og * 4]);
                ulonglong2 w01 = wp[0], w23 = wp[1];
                GEMM8(acc2, w01, w23, va, vb);
            }
        }
    }

    float* dbp = g_d + (size_t)b * BNk * HWk + p0;
#pragma unroll
    for (int o = 0; o < 4; o++) {
        float2 f0 = unpack2(acc2[0][o]);
        float2 f1 = unpack2(acc2[1][o]);
        *reinterpret_cast<float2*>(dbp + (size_t)(og * 4 + o) * HWk + 2 * g)      = f0;
        *reinterpret_cast<float2*>(dbp + (size_t)(og * 4 + o) * HWk + 32 + 2 * g) = f1;
    }
}

// -------- kernel D: 1x1 up conv + residual + BN stats, 4px x 4oc ------------
__global__ void __launch_bounds__(256, 5) up_kernel(const float* __restrict__ x,
                                                    float* __restrict__ out) {
    __shared__ __align__(16) float vsm[32][64];    // 8KB d values
    __shared__ __align__(16) ull   wsm2[32][64];   // 16KB dup-packed weights
    int tid = threadIdx.x;
    int g   = tid & 15;
    int og  = tid >> 4;
    int oh  = blockIdx.y;        // oc quarter: [oh*64, oh*64+64)
    int bp  = blockIdx.x * 64;
    int b   = bp >> 14;
    int p0  = bp & 16383;

    ull acc2[2][4];
#pragma unroll
    for (int j = 0; j < 2; j++)
#pragma unroll
        for (int o = 0; o < 4; o++) acc2[j][o] = 0ull;

    const float* db = g_d + (size_t)b * BNk * HWk + p0;

#pragma unroll 1
    for (int c0 = 0; c0 < 64; c0 += 32) {
        __syncthreads();
        {   // stage dup-packed weights: wsm2[c][o] = dup(g_uwT[(c0+c)*256 + oh*64 + o])
            const float4* usrc = reinterpret_cast<const float4*>(g_uwT);
#pragma unroll
            for (int j = tid; j < 512; j += 256) {
                int c = j >> 4, o4 = j & 15;
                float4 w = usrc[(c0 + c) * 64 + oh * 16 + o4];
                ulonglong2* dst = reinterpret_cast<ulonglong2*>(&wsm2[c][o4 * 4]);
                dst[0] = make_ulonglong2(pack2(w.x), pack2(w.y));
                dst[1] = make_ulonglong2(pack2(w.z), pack2(w.w));
            }
        }
        {   // stage d tile
#pragma unroll
            for (int j = tid; j < 512; j += 256) {
                int c = j >> 4, p4 = j & 15;
                *reinterpret_cast<float4*>(&vsm[c][p4 * 4]) =
                    *reinterpret_cast<const float4*>(db + (size_t)(c0 + c) * HWk + p4 * 4);
            }
        }
        __syncthreads();

#pragma unroll 4
        for (int c = 0; c < 32; c++) {
            const ull* vp = reinterpret_cast<const ull*>(&vsm[c][0]);
            ull va = vp[g], vb = vp[16 + g];
            const ulonglong2* wp = reinterpret_cast<const ulonglong2*>(&wsm2[c][og * 4]);
            ulonglong2 w01 = wp[0], w23 = wp[1];
            GEMM8(acc2, w01, w23, va, vb);
        }
    }

    // epilogue: +x, write, BN partial sums (16-lane groups share oc-group)
    const float* xb = x   + (size_t)b * Ck * HWk + p0;
    float*       ob = out + (size_t)b * Ck * HWk + p0;
    int ocb = oh * 64 + og * 4;
#pragma unroll
    for (int o = 0; o < 4; o++) {
        float2 f0 = unpack2(acc2[0][o]);
        float2 f1 = unpack2(acc2[1][o]);
        const float* xr = xb + (size_t)(ocb + o) * HWk;
        float*       orow = ob + (size_t)(ocb + o) * HWk;
        float2 x0 = *reinterpret_cast<const float2*>(xr + 2 * g);
        float2 x1 = *reinterpret_cast<const float2*>(xr + 32 + 2 * g);
        float2 y0 = make_float2(x0.x + f0.x, x0.y + f0.y);
        float2 y1 = make_float2(x1.x + f1.x, x1.y + f1.y);
        *reinterpret_cast<float2*>(orow + 2 * g)      = y0;
        *reinterpret_cast<float2*>(orow + 32 + 2 * g) = y1;

        float ws = y0.x + y0.y + y1.x + y1.y;
        float wq = y0.x * y0.x + y0.y * y0.y + y1.x * y1.x + y1.y * y1.y;
#pragma unroll
        for (int d = 8; d; d >>= 1) {
            ws += __shfl_xor_sync(0xffffffffu, ws, d);
            wq += __shfl_xor_sync(0xffffffffu, wq, d);
        }
        if ((tid & 15) == 0) {
            atomicAdd(&g_sum[ocb + o],   ws);
            atomicAdd(&g_sumsq[ocb + o], wq);
        }
    }
}

// -------- kernel E: BatchNorm (training stats) + SiLU, in place --------
__global__ void __launch_bounds__(256) norm_kernel(float* __restrict__ out,
                                                   const float* __restrict__ gamma,
                                                   const float* __restrict__ beta) {
    const float invN = 1.f / (float)(Bk * HWk);   // 1/65536
    size_t i = (size_t)blockIdx.x * 256 + threadIdx.x;   // float4 index
    int ch = (int)((i >> 12) & 255);                      // 4096 float4 per channel

    float mean = g_sum[ch] * invN;
    float var  = g_sumsq[ch] * invN - mean * mean;
    float r    = rsqrtf(var + 1e-5f);
    float sc   = r * __ldg(gamma + ch);
    float sh   = __ldg(beta + ch) - mean * sc;

    float4* o4 = reinterpret_cast<float4*>(out);
    float4 v = o4[i];
    float h;
    h = v.x * sc + sh; v.x = h / (1.f + __expf(-h));
    h = v.y * sc + sh; v.y = h / (1.f + __expf(-h));
    h = v.z * sc + sh; v.z = h / (1.f + __expf(-h));
    h = v.w * sc + sh; v.w = h / (1.f + __expf(-h));
    o4[i] = v;
}

// -------- launch --------
extern "C" void kernel_launch(void* const* d_in, const int* in_sizes, int n_in,
                              void* d_out, int out_size) {
    const float* x      = (const float*)d_in[0];
    const float* down_w = (const float*)d_in[1];
    const float* off_w  = (const float*)d_in[2];
    const float* off_b  = (const float*)d_in[3];
    const float* mask_w = (const float*)d_in[4];
    const float* mask_b = (const float*)d_in[5];
    const float* def_w  = (const float*)d_in[6];
    const float* def_b  = (const float*)d_in[7];
    const float* up_w   = (const float*)d_in[8];
    const float* gamma  = (const float*)d_in[9];
    const float* beta   = (const float*)d_in[10];
    float* out = (float*)d_out;

    prep_kernel<<<144, 256>>>(down_w, off_w, off_b, mask_w, mask_b, def_w, up_w);
    down_kernel<<<1024, 256>>>(x);
    offmask_kernel<<<dim3(Hk / 2, Bk), 256>>>();
    deform_kernel<<<1024, 256>>>(def_b);
    up_kernel<<<dim3(1024, 4), 256>>>(x, out);
    norm_kernel<<<(Bk * Ck * HWk) / 4 / 256, 256>>>(out, gamma, beta);
}